// round 1
// baseline (speedup 1.0000x reference)
#include <cuda_runtime.h>
#include <math.h>

#define BCN   512          // B*C
#define LBK   1024
#define PREDN 256
#define TOT   1280
#define DEL   64
#define DPD   128
#define NKR   971          // key rows (T)
#define NQR   244          // query rows (UP)
#define NROWS 1215         // NKR + NQR
#define FLATN 15616        // NQR*DEL

// ---------------- scratch (module-load allocated, no runtime alloc) -----------
__device__ float g_kq[(size_t)BCN * NROWS * DPD];   // layernormed k rows then q rows
__device__ float g_flat[(size_t)BCN * FLATN];       // attention outputs (preds, flattened)
__device__ float g_hpart[4 * BCN * PREDN];          // split-K partials of flat@W1

__device__ __forceinline__ float series_at(const float* __restrict__ lb,
                                           const float* __restrict__ fp,
                                           int bc, int i) {
    return (i < LBK) ? lb[bc * LBK + i] : fp[bc * PREDN + (i - LBK)];
}

// ---------------- Kernel A: window proj + bias + PE + LayerNorm ---------------
#define A_ROWS 48
#define A_G    8
__global__ void proj_ln_kernel(const float* __restrict__ lb, const float* __restrict__ fp,
                               const float* __restrict__ Wp, const float* __restrict__ bp,
                               const float* __restrict__ pe, const float* __restrict__ lng,
                               const float* __restrict__ lnb) {
    __shared__ float Ws[DEL * DPD];       // 32 KB
    __shared__ float ws[A_G][DEL];
    __shared__ float red[4][A_G][2];
    const int bc   = blockIdx.y;
    const int tid  = threadIdx.x;         // 128
    const int e    = tid;
    const int lane = tid & 31, warp = tid >> 5;

    for (int i = tid; i < DEL * DPD; i += 128) Ws[i] = Wp[i];
    const float bpv = bp[e], gv = lng[e], bv = lnb[e];
    const int t_base = blockIdx.x * A_ROWS;

    for (int g = 0; g < A_ROWS / A_G; ++g) {
        const int t0 = t_base + g * A_G;
        if (t0 >= NROWS) break;
        __syncthreads();
        // load A_G windows of 64 series values
        for (int i = tid; i < A_G * DEL; i += 128) {
            int r = i / DEL, d = i % DEL;
            int t = t0 + r;
            float v = 0.f;
            if (t < NROWS) {
                int s0 = (t < NKR) ? t : (t + 1);   // q row u starts at 972+u = t+1
                v = series_at(lb, fp, bc, s0 + d);
            }
            ws[r][d] = v;
        }
        __syncthreads();

        float acc[A_G];
        #pragma unroll
        for (int r = 0; r < A_G; ++r) acc[r] = 0.f;
        #pragma unroll 8
        for (int d = 0; d < DEL; ++d) {
            float w = Ws[d * DPD + e];
            #pragma unroll
            for (int r = 0; r < A_G; ++r) acc[r] += ws[r][d] * w;
        }

        float x[A_G], s[A_G], q[A_G];
        #pragma unroll
        for (int r = 0; r < A_G; ++r) {
            int t = t0 + r;
            float pev = (t < NROWS) ? pe[t * DPD + e] : 0.f;  // pe row == t for k and q
            x[r] = acc[r] + bpv + pev;
            s[r] = x[r];
            q[r] = x[r] * x[r];
        }
        #pragma unroll
        for (int off = 16; off; off >>= 1) {
            #pragma unroll
            for (int r = 0; r < A_G; ++r) {
                s[r] += __shfl_xor_sync(0xffffffffu, s[r], off);
                q[r] += __shfl_xor_sync(0xffffffffu, q[r], off);
            }
        }
        if (lane == 0) {
            #pragma unroll
            for (int r = 0; r < A_G; ++r) { red[warp][r][0] = s[r]; red[warp][r][1] = q[r]; }
        }
        __syncthreads();
        #pragma unroll
        for (int r = 0; r < A_G; ++r) {
            int t = t0 + r;
            if (t >= NROWS) continue;
            float ts = red[0][r][0] + red[1][r][0] + red[2][r][0] + red[3][r][0];
            float tq = red[0][r][1] + red[1][r][1] + red[2][r][1] + red[3][r][1];
            float mean = ts * (1.f / DPD);
            float var  = tq * (1.f / DPD) - mean * mean;
            float inv  = rsqrtf(var + 1e-5f);
            g_kq[((size_t)bc * NROWS + t) * DPD + e] = (x[r] - mean) * inv * gv + bv;
        }
    }
}

// ---------------- Kernel B: flash attention + PV (V read from raw series) -----
#define QT   64
#define KT   64
#define QSTR 130
#define PSTR 68
#define ATTN_SMEM_FLOATS (QT*QSTR + KT*QSTR + QT*PSTR + TOT)   // 22272
#define ATTN_SMEM_BYTES  (ATTN_SMEM_FLOATS * 4)                 // 89088

__global__ void attn_kernel(const float* __restrict__ lb, const float* __restrict__ fp) {
    extern __shared__ float sm[];
    float* qs = sm;
    float* ks = qs + QT * QSTR;
    float* ps = ks + KT * QSTR;
    float* ss = ps + QT * PSTR;

    const int bc  = blockIdx.y;
    const int qt0 = blockIdx.x * QT;
    const int nq  = min(QT, NQR - qt0);
    const int tid = threadIdx.x;          // 256
    const int ig  = tid >> 4;             // 0..15 -> q rows ig*4..ig*4+3
    const int jg  = tid & 15;             // 0..15 -> k cols / d cols y*16+jg

    for (int i = tid; i < TOT; i += 256) ss[i] = series_at(lb, fp, bc, i);

    const float* qbase = g_kq + ((size_t)bc * NROWS + NKR + qt0) * DPD;
    for (int i = tid; i < QT * DPD; i += 256) {
        int r = i >> 7, e = i & 127;
        qs[r * QSTR + e] = (r < nq) ? qbase[r * DPD + e] : 0.f;
    }

    float m[4], l[4], acc[4][4];
    #pragma unroll
    for (int x = 0; x < 4; ++x) {
        m[x] = -1e30f; l[x] = 0.f;
        #pragma unroll
        for (int y = 0; y < 4; ++y) acc[x][y] = 0.f;
    }
    __syncthreads();

    const float SCALE = 0.088388347648318447f;  // 1/sqrt(128)

    for (int kt0 = 0; kt0 < NKR; kt0 += KT) {
        const int nk = min(KT, NKR - kt0);
        const float* kbase = g_kq + ((size_t)bc * NROWS + kt0) * DPD;
        for (int i = tid; i < KT * DPD; i += 256) {
            int r = i >> 7, e = i & 127;
            ks[r * QSTR + e] = (r < nk) ? kbase[r * DPD + e] : 0.f;
        }
        __syncthreads();

        float sc[4][4];
        #pragma unroll
        for (int x = 0; x < 4; ++x)
            #pragma unroll
            for (int y = 0; y < 4; ++y) sc[x][y] = 0.f;

        #pragma unroll 4
        for (int e = 0; e < DPD; e += 2) {
            float2 qv[4], kv[4];
            #pragma unroll
            for (int x = 0; x < 4; ++x) qv[x] = *(const float2*)(qs + (ig * 4 + x) * QSTR + e);
            #pragma unroll
            for (int y = 0; y < 4; ++y) kv[y] = *(const float2*)(ks + (y * 16 + jg) * QSTR + e);
            #pragma unroll
            for (int x = 0; x < 4; ++x)
                #pragma unroll
                for (int y = 0; y < 4; ++y)
                    sc[x][y] += qv[x].x * kv[y].x + qv[x].y * kv[y].y;
        }

        // scale + mask invalid keys
        #pragma unroll
        for (int y = 0; y < 4; ++y) {
            bool valid = (y * 16 + jg) < nk;
            #pragma unroll
            for (int x = 0; x < 4; ++x)
                sc[x][y] = valid ? sc[x][y] * SCALE : -1e30f;
        }

        // online softmax
        #pragma unroll
        for (int x = 0; x < 4; ++x) {
            float rmx = sc[x][0];
            #pragma unroll
            for (int y = 1; y < 4; ++y) rmx = fmaxf(rmx, sc[x][y]);
            #pragma unroll
            for (int off = 8; off; off >>= 1)
                rmx = fmaxf(rmx, __shfl_xor_sync(0xffffffffu, rmx, off));
            float mn    = fmaxf(m[x], rmx);
            float alpha = __expf(m[x] - mn);
            float rs = 0.f;
            #pragma unroll
            for (int y = 0; y < 4; ++y) {
                float p = __expf(sc[x][y] - mn);
                ps[(ig * 4 + x) * PSTR + y * 16 + jg] = p;
                rs += p;
            }
            #pragma unroll
            for (int off = 8; off; off >>= 1)
                rs += __shfl_xor_sync(0xffffffffu, rs, off);
            l[x] = l[x] * alpha + rs;
            m[x] = mn;
            #pragma unroll
            for (int y = 0; y < 4; ++y) acc[x][y] *= alpha;
        }
        __syncthreads();

        // PV: v[j][d] = series[kt0+1+j+d]
        const float* vv = ss + kt0 + 1;
        #pragma unroll 4
        for (int j = 0; j < KT; ++j) {
            float pr[4], vr[4];
            #pragma unroll
            for (int x = 0; x < 4; ++x) pr[x] = ps[(ig * 4 + x) * PSTR + j];
            #pragma unroll
            for (int y = 0; y < 4; ++y) vr[y] = vv[j + y * 16 + jg];
            #pragma unroll
            for (int x = 0; x < 4; ++x)
                #pragma unroll
                for (int y = 0; y < 4; ++y) acc[x][y] += pr[x] * vr[y];
        }
        __syncthreads();
    }

    #pragma unroll
    for (int x = 0; x < 4; ++x) {
        int i = qt0 + ig * 4 + x;
        if (i >= NQR) continue;
        float linv = 1.f / l[x];
        #pragma unroll
        for (int y = 0; y < 4; ++y)
            g_flat[(size_t)bc * FLATN + i * DEL + y * 16 + jg] = acc[x][y] * linv;
    }
}

// ---------------- Kernel C1: flat @ W1 split-K partials -----------------------
__global__ void mlp1_kernel(const float* __restrict__ W1) {
    __shared__ float As[32 * 68];
    __shared__ float Bs[64 * 64];
    const int n0  = blockIdx.x * 64;
    const int bc0 = blockIdx.y * 32;
    const int f0  = blockIdx.z * 3904;   // 61 k-tiles of 64
    const int tid = threadIdx.x;         // 256
    const int bg  = tid >> 4;            // 0..15 -> bc rows bg, bg+16
    const int nl  = tid & 15;            // -> cols nl*4..nl*4+3

    float acc0[4] = {0.f, 0.f, 0.f, 0.f};
    float acc1[4] = {0.f, 0.f, 0.f, 0.f};

    for (int kt = 0; kt < 61; ++kt) {
        const int k0 = f0 + kt * 64;
        __syncthreads();
        for (int i = tid; i < 32 * 64; i += 256) {
            int r = i >> 6, c = i & 63;
            As[r * 68 + c] = g_flat[(size_t)(bc0 + r) * FLATN + k0 + c];
        }
        for (int i = tid; i < 64 * 64; i += 256) {
            int r = i >> 6, c = i & 63;
            Bs[i] = W1[(size_t)(k0 + r) * PREDN + n0 + c];
        }
        __syncthreads();
        #pragma unroll 8
        for (int kk = 0; kk < 64; ++kk) {
            float a0 = As[bg * 68 + kk];
            float a1 = As[(bg + 16) * 68 + kk];
            float4 b = *(const float4*)(Bs + kk * 64 + nl * 4);
            acc0[0] += a0 * b.x; acc0[1] += a0 * b.y; acc0[2] += a0 * b.z; acc0[3] += a0 * b.w;
            acc1[0] += a1 * b.x; acc1[1] += a1 * b.y; acc1[2] += a1 * b.z; acc1[3] += a1 * b.w;
        }
    }
    float* outp = g_hpart + ((size_t)blockIdx.z * BCN + bc0) * PREDN + n0 + nl * 4;
    *(float4*)(outp + (size_t)bg * PREDN)        = make_float4(acc0[0], acc0[1], acc0[2], acc0[3]);
    *(float4*)(outp + (size_t)(bg + 16) * PREDN) = make_float4(acc1[0], acc1[1], acc1[2], acc1[3]);
}

// ---------------- Kernel C2: reduce partials + bias + GELU + @W2 + bias -------
__global__ void mlp2_kernel(const float* __restrict__ b1, const float* __restrict__ W2,
                            const float* __restrict__ b2, float* __restrict__ out) {
    __shared__ float hs[8][PREDN];
    const int bc0 = blockIdx.x * 8;
    const int tid = threadIdx.x;   // 256

    for (int i = tid; i < 8 * PREDN; i += 256) {
        int r = i >> 8, n = i & 255;
        int bc = bc0 + r;
        float v = b1[n];
        #pragma unroll
        for (int ks = 0; ks < 4; ++ks)
            v += g_hpart[((size_t)ks * BCN + bc) * PREDN + n];
        hs[r][n] = 0.5f * v * (1.f + erff(v * 0.70710678118654752f));  // exact GELU
    }
    __syncthreads();

    const int n = tid;
    float acc[8];
    #pragma unroll
    for (int r = 0; r < 8; ++r) acc[r] = 0.f;
    #pragma unroll 4
    for (int mm = 0; mm < PREDN; ++mm) {
        float w = W2[mm * PREDN + n];
        #pragma unroll
        for (int r = 0; r < 8; ++r) acc[r] += hs[r][mm] * w;
    }
    float bb = b2[n];
    #pragma unroll
    for (int r = 0; r < 8; ++r)
        out[(size_t)(bc0 + r) * PREDN + n] = acc[r] + bb;
}

// ---------------- launch ------------------------------------------------------
extern "C" void kernel_launch(void* const* d_in, const int* in_sizes, int n_in,
                              void* d_out, int out_size) {
    const float* lb  = (const float*)d_in[0];
    const float* fp  = (const float*)d_in[1];
    const float* Wp  = (const float*)d_in[2];
    const float* bp  = (const float*)d_in[3];
    const float* pe  = (const float*)d_in[4];
    const float* lng = (const float*)d_in[5];
    const float* lnb = (const float*)d_in[6];
    const float* W1  = (const float*)d_in[7];
    const float* b1  = (const float*)d_in[8];
    const float* W2  = (const float*)d_in[9];
    const float* b2  = (const float*)d_in[10];
    float* out = (float*)d_out;

    cudaFuncSetAttribute(attn_kernel, cudaFuncAttributeMaxDynamicSharedMemorySize,
                         ATTN_SMEM_BYTES);

    proj_ln_kernel<<<dim3((NROWS + A_ROWS - 1) / A_ROWS, BCN), 128>>>(lb, fp, Wp, bp, pe, lng, lnb);
    attn_kernel<<<dim3((NQR + QT - 1) / QT, BCN), 256, ATTN_SMEM_BYTES>>>(lb, fp);
    mlp1_kernel<<<dim3(4, 16, 4), 256>>>(W1);
    mlp2_kernel<<<BCN / 8, 256>>>(b1, W2, b2, out);
}

// round 2
// speedup vs baseline: 1.4826x; 1.4826x over previous
#include <cuda_runtime.h>
#include <math.h>
#include <stdint.h>

#define BCN   512          // B*C
#define LBK   1024
#define PREDN 256
#define TOT   1280
#define DEL   64
#define DPD   128
#define NKR   971          // key rows (T)
#define NQR   244          // query rows (UP)
#define NROWS 1215         // NKR + NQR
#define FLATN 15616        // NQR*DEL

// ---------------- scratch (module-load allocated, no runtime alloc) -----------
__device__ float g_kq[(size_t)BCN * NROWS * DPD];   // layernormed k rows then q rows
__device__ float g_flat[(size_t)BCN * FLATN];       // attention outputs (preds, flattened)
__device__ float g_hpart[4 * BCN * PREDN];          // split-K partials of flat@W1

__device__ __forceinline__ float series_at(const float* __restrict__ lb,
                                           const float* __restrict__ fp,
                                           int bc, int i) {
    return (i < LBK) ? lb[bc * LBK + i] : fp[bc * PREDN + (i - LBK)];
}

// ---------------- mma helpers -------------------------------------------------
__device__ __forceinline__ void mma8(float c[4], const uint32_t a[4], const uint32_t b[2]) {
    asm volatile(
        "mma.sync.aligned.m16n8k8.row.col.f32.tf32.tf32.f32 "
        "{%0,%1,%2,%3}, {%4,%5,%6,%7}, {%8,%9}, {%0,%1,%2,%3};\n"
        : "+f"(c[0]), "+f"(c[1]), "+f"(c[2]), "+f"(c[3])
        : "r"(a[0]), "r"(a[1]), "r"(a[2]), "r"(a[3]), "r"(b[0]), "r"(b[1]));
}

__device__ __forceinline__ void split2(float x, uint32_t& hi, uint32_t& lo) {
    uint32_t h = __float_as_uint(x) & 0xffffe000u;
    hi = h;
    lo = __float_as_uint(x - __uint_as_float(h));
}

// ---------------- Kernel A: window proj + bias + PE + LayerNorm ---------------
#define A_ROWS 48
#define A_G    8
__global__ void proj_ln_kernel(const float* __restrict__ lb, const float* __restrict__ fp,
                               const float* __restrict__ Wp, const float* __restrict__ bp,
                               const float* __restrict__ pe, const float* __restrict__ lng,
                               const float* __restrict__ lnb) {
    __shared__ float Ws[DEL * DPD];       // 32 KB
    __shared__ float ws[A_G][DEL];
    __shared__ float red[4][A_G][2];
    const int bc   = blockIdx.y;
    const int tid  = threadIdx.x;         // 128
    const int e    = tid;
    const int lane = tid & 31, warp = tid >> 5;

    for (int i = tid; i < DEL * DPD; i += 128) Ws[i] = Wp[i];
    const float bpv = bp[e], gv = lng[e], bv = lnb[e];
    const int t_base = blockIdx.x * A_ROWS;

    for (int g = 0; g < A_ROWS / A_G; ++g) {
        const int t0 = t_base + g * A_G;
        if (t0 >= NROWS) break;
        __syncthreads();
        for (int i = tid; i < A_G * DEL; i += 128) {
            int r = i / DEL, d = i % DEL;
            int t = t0 + r;
            float v = 0.f;
            if (t < NROWS) {
                int s0 = (t < NKR) ? t : (t + 1);
                v = series_at(lb, fp, bc, s0 + d);
            }
            ws[r][d] = v;
        }
        __syncthreads();

        float acc[A_G];
        #pragma unroll
        for (int r = 0; r < A_G; ++r) acc[r] = 0.f;
        #pragma unroll 8
        for (int d = 0; d < DEL; ++d) {
            float w = Ws[d * DPD + e];
            #pragma unroll
            for (int r = 0; r < A_G; ++r) acc[r] += ws[r][d] * w;
        }

        float x[A_G], s[A_G], q[A_G];
        #pragma unroll
        for (int r = 0; r < A_G; ++r) {
            int t = t0 + r;
            float pev = (t < NROWS) ? pe[t * DPD + e] : 0.f;
            x[r] = acc[r] + bpv + pev;
            s[r] = x[r];
            q[r] = x[r] * x[r];
        }
        #pragma unroll
        for (int off = 16; off; off >>= 1) {
            #pragma unroll
            for (int r = 0; r < A_G; ++r) {
                s[r] += __shfl_xor_sync(0xffffffffu, s[r], off);
                q[r] += __shfl_xor_sync(0xffffffffu, q[r], off);
            }
        }
        if (lane == 0) {
            #pragma unroll
            for (int r = 0; r < A_G; ++r) { red[warp][r][0] = s[r]; red[warp][r][1] = q[r]; }
        }
        __syncthreads();
        #pragma unroll
        for (int r = 0; r < A_G; ++r) {
            int t = t0 + r;
            if (t >= NROWS) continue;
            float ts = red[0][r][0] + red[1][r][0] + red[2][r][0] + red[3][r][0];
            float tq = red[0][r][1] + red[1][r][1] + red[2][r][1] + red[3][r][1];
            float mean = ts * (1.f / DPD);
            float var  = tq * (1.f / DPD) - mean * mean;
            float inv  = rsqrtf(var + 1e-5f);
            g_kq[((size_t)bc * NROWS + t) * DPD + e] = (x[r] - mean) * inv * gv + bv;
        }
    }
}

// ---------------- Kernel B: flash attention on tensor cores (3xtf32) ----------
#define STR  132
#define AQT  128
#define AKT  128
#define ASM_FLOATS (3*128*STR + TOT + 3*128 + 512)
#define ASM_BYTES  (ASM_FLOATS * 4)      // 211456

__global__ void __launch_bounds__(256, 1)
attn_kernel(const float* __restrict__ lb, const float* __restrict__ fp) {
    extern __shared__ float sm[];
    float* qs     = sm;                   // [128][STR]
    float* ks     = sm + 128 * STR;       // [128][STR]
    float* ps     = sm + 2 * 128 * STR;   // [128][STR]
    float* ss     = sm + 3 * 128 * STR;   // [TOT]
    float* m_s    = ss + TOT;             // [128]
    float* l_s    = m_s + 128;            // [128]
    float* al_s   = l_s + 128;            // [128]
    float* rmax_s = al_s + 128;           // [2][128]
    float* rsum_s = rmax_s + 256;         // [2][128]

    const int bc  = blockIdx.y;
    const int qt0 = blockIdx.x * AQT;
    const int tid = threadIdx.x;
    const int warp = tid >> 5, lane = tid & 31;
    const int g = lane >> 2, t = lane & 3;

    for (int i = tid; i < TOT; i += 256) ss[i] = series_at(lb, fp, bc, i);

    const float* qb = g_kq + ((size_t)bc * NROWS + NKR + qt0) * DPD;
    for (int i = tid; i < 128 * 32; i += 256) {
        int r = i >> 5, c = i & 31;
        float4 v = make_float4(0.f, 0.f, 0.f, 0.f);
        if (qt0 + r < NQR) v = *(const float4*)(qb + (size_t)r * DPD + c * 4);
        *(float4*)(qs + r * STR + c * 4) = v;
    }
    if (tid < 128) { m_s[tid] = -1e30f; l_s[tid] = 0.f; }

    const int s_q0 = (warp >> 1) * 32;    // S warp tile: 32q x 64k
    const int s_k0 = (warp & 1) * 64;
    const int o_q0 = (warp >> 1) * 32;    // O warp tile: 32q x 32d
    const int o_d0 = (warp & 1) * 32;

    float cO[2][4][4];
    #pragma unroll
    for (int mi = 0; mi < 2; ++mi)
        #pragma unroll
        for (int ni = 0; ni < 4; ++ni)
            #pragma unroll
            for (int i = 0; i < 4; ++i) cO[mi][ni][i] = 0.f;

    __syncthreads();

    const float SCALE = 0.088388347648318447f;  // 1/sqrt(128)

    for (int kt0 = 0; kt0 < NKR; kt0 += AKT) {
        // ---- load K chunk ----
        const float* kb = g_kq + ((size_t)bc * NROWS + kt0) * DPD;
        for (int i = tid; i < 128 * 32; i += 256) {
            int r = i >> 5, c = i & 31;
            float4 v = make_float4(0.f, 0.f, 0.f, 0.f);
            if (kt0 + r < NKR) v = *(const float4*)(kb + (size_t)r * DPD + c * 4);
            *(float4*)(ks + r * STR + c * 4) = v;
        }
        __syncthreads();

        // ---- S = Q @ K^T (3xtf32) ----
        float cS[2][8][4];
        #pragma unroll
        for (int mi = 0; mi < 2; ++mi)
            #pragma unroll
            for (int ni = 0; ni < 8; ++ni)
                #pragma unroll
                for (int i = 0; i < 4; ++i) cS[mi][ni][i] = 0.f;

        #pragma unroll 2
        for (int e = 0; e < DPD; e += 8) {
            uint32_t ah[2][4], al[2][4];
            #pragma unroll
            for (int mi = 0; mi < 2; ++mi)
                #pragma unroll
                for (int i = 0; i < 4; ++i)
                    split2(qs[(s_q0 + mi * 16 + g + (i & 1) * 8) * STR + e + t + (i >> 1) * 4],
                           ah[mi][i], al[mi][i]);
            uint32_t bh[8][2], bl[8][2];
            #pragma unroll
            for (int ni = 0; ni < 8; ++ni) {
                int kr = (s_k0 + ni * 8 + g) * STR;
                split2(ks[kr + e + t],     bh[ni][0], bl[ni][0]);
                split2(ks[kr + e + t + 4], bh[ni][1], bl[ni][1]);
            }
            #pragma unroll
            for (int mi = 0; mi < 2; ++mi)
                #pragma unroll
                for (int ni = 0; ni < 8; ++ni) {
                    mma8(cS[mi][ni], ah[mi], bh[ni]);
                    mma8(cS[mi][ni], ah[mi], bl[ni]);
                    mma8(cS[mi][ni], al[mi], bh[ni]);
                }
        }

        // ---- scale + mask + row max ----
        float rmx[2][2];
        #pragma unroll
        for (int mi = 0; mi < 2; ++mi) { rmx[mi][0] = -1e30f; rmx[mi][1] = -1e30f; }
        #pragma unroll
        for (int mi = 0; mi < 2; ++mi)
            #pragma unroll
            for (int ni = 0; ni < 8; ++ni)
                #pragma unroll
                for (int i = 0; i < 4; ++i) {
                    int col = s_k0 + ni * 8 + 2 * t + (i & 1);
                    float v = (kt0 + col < NKR) ? cS[mi][ni][i] * SCALE : -1e30f;
                    cS[mi][ni][i] = v;
                    rmx[mi][i >> 1] = fmaxf(rmx[mi][i >> 1], v);
                }
        #pragma unroll
        for (int mi = 0; mi < 2; ++mi)
            #pragma unroll
            for (int h = 0; h < 2; ++h) {
                rmx[mi][h] = fmaxf(rmx[mi][h], __shfl_xor_sync(0xffffffffu, rmx[mi][h], 1));
                rmx[mi][h] = fmaxf(rmx[mi][h], __shfl_xor_sync(0xffffffffu, rmx[mi][h], 2));
            }
        if (t == 0) {
            #pragma unroll
            for (int mi = 0; mi < 2; ++mi)
                #pragma unroll
                for (int h = 0; h < 2; ++h)
                    rmax_s[(warp & 1) * 128 + s_q0 + mi * 16 + g + h * 8] = rmx[mi][h];
        }
        __syncthreads();

        if (tid < 128) {
            float mo = m_s[tid];
            float mn = fmaxf(mo, fmaxf(rmax_s[tid], rmax_s[128 + tid]));
            al_s[tid] = __expf(mo - mn);
            m_s[tid] = mn;
        }
        __syncthreads();

        // ---- P = exp(S - m), store + row sums ----
        float mrow[2][2];
        #pragma unroll
        for (int mi = 0; mi < 2; ++mi)
            #pragma unroll
            for (int h = 0; h < 2; ++h)
                mrow[mi][h] = m_s[s_q0 + mi * 16 + g + h * 8];

        float rs[2][2] = {{0.f, 0.f}, {0.f, 0.f}};
        #pragma unroll
        for (int mi = 0; mi < 2; ++mi)
            #pragma unroll
            for (int ni = 0; ni < 8; ++ni) {
                float p0 = __expf(cS[mi][ni][0] - mrow[mi][0]);
                float p1 = __expf(cS[mi][ni][1] - mrow[mi][0]);
                float p2 = __expf(cS[mi][ni][2] - mrow[mi][1]);
                float p3 = __expf(cS[mi][ni][3] - mrow[mi][1]);
                rs[mi][0] += p0 + p1;
                rs[mi][1] += p2 + p3;
                int cbase = s_k0 + ni * 8 + 2 * t;
                *(float2*)(ps + (s_q0 + mi * 16 + g) * STR + cbase)     = make_float2(p0, p1);
                *(float2*)(ps + (s_q0 + mi * 16 + g + 8) * STR + cbase) = make_float2(p2, p3);
            }
        #pragma unroll
        for (int mi = 0; mi < 2; ++mi)
            #pragma unroll
            for (int h = 0; h < 2; ++h) {
                rs[mi][h] += __shfl_xor_sync(0xffffffffu, rs[mi][h], 1);
                rs[mi][h] += __shfl_xor_sync(0xffffffffu, rs[mi][h], 2);
            }
        if (t == 0) {
            #pragma unroll
            for (int mi = 0; mi < 2; ++mi)
                #pragma unroll
                for (int h = 0; h < 2; ++h)
                    rsum_s[(warp & 1) * 128 + s_q0 + mi * 16 + g + h * 8] = rs[mi][h];
        }
        __syncthreads();

        if (tid < 128)
            l_s[tid] = l_s[tid] * al_s[tid] + rsum_s[tid] + rsum_s[128 + tid];

        // ---- O = O*alpha + P @ V  (V[j][d] = series[kt0+1+j+d]) ----
        float af[2][2];
        #pragma unroll
        for (int mi = 0; mi < 2; ++mi)
            #pragma unroll
            for (int h = 0; h < 2; ++h)
                af[mi][h] = al_s[o_q0 + mi * 16 + g + h * 8];
        #pragma unroll
        for (int mi = 0; mi < 2; ++mi)
            #pragma unroll
            for (int ni = 0; ni < 4; ++ni)
                #pragma unroll
                for (int i = 0; i < 4; ++i)
                    cO[mi][ni][i] *= af[mi][i >> 1];

        const float* vb = ss + kt0 + 1;
        #pragma unroll 2
        for (int kk = 0; kk < AKT; kk += 8) {
            uint32_t ph[2][4], pl[2][4];
            #pragma unroll
            for (int mi = 0; mi < 2; ++mi)
                #pragma unroll
                for (int i = 0; i < 4; ++i)
                    split2(ps[(o_q0 + mi * 16 + g + (i & 1) * 8) * STR + kk + t + (i >> 1) * 4],
                           ph[mi][i], pl[mi][i]);
            uint32_t vh[4][2], vl[4][2];
            #pragma unroll
            for (int ni = 0; ni < 4; ++ni) {
                int d = o_d0 + ni * 8 + g;
                split2(vb[kk + t + d],     vh[ni][0], vl[ni][0]);
                split2(vb[kk + t + 4 + d], vh[ni][1], vl[ni][1]);
            }
            #pragma unroll
            for (int mi = 0; mi < 2; ++mi)
                #pragma unroll
                for (int ni = 0; ni < 4; ++ni) {
                    mma8(cO[mi][ni], ph[mi], vh[ni]);
                    mma8(cO[mi][ni], ph[mi], vl[ni]);
                    mma8(cO[mi][ni], pl[mi], vh[ni]);
                }
        }
        // no sync needed: next-chunk __syncthreads (after ks load) orders everything
    }

    __syncthreads();
    float li[2][2];
    #pragma unroll
    for (int mi = 0; mi < 2; ++mi)
        #pragma unroll
        for (int h = 0; h < 2; ++h)
            li[mi][h] = 1.f / l_s[o_q0 + mi * 16 + g + h * 8];

    #pragma unroll
    for (int mi = 0; mi < 2; ++mi)
        #pragma unroll
        for (int ni = 0; ni < 4; ++ni) {
            int r0 = qt0 + o_q0 + mi * 16 + g;
            int d  = o_d0 + ni * 8 + 2 * t;
            if (r0 < NQR)
                *(float2*)(g_flat + (size_t)bc * FLATN + r0 * DEL + d) =
                    make_float2(cO[mi][ni][0] * li[mi][0], cO[mi][ni][1] * li[mi][0]);
            if (r0 + 8 < NQR)
                *(float2*)(g_flat + (size_t)bc * FLATN + (r0 + 8) * DEL + d) =
                    make_float2(cO[mi][ni][2] * li[mi][1], cO[mi][ni][3] * li[mi][1]);
        }
}

// ---------------- Kernel C1: flat @ W1 split-K partials -----------------------
__global__ void mlp1_kernel(const float* __restrict__ W1) {
    __shared__ float As[32 * 68];
    __shared__ float Bs[64 * 64];
    const int n0  = blockIdx.x * 64;
    const int bc0 = blockIdx.y * 32;
    const int f0  = blockIdx.z * 3904;
    const int tid = threadIdx.x;
    const int bg  = tid >> 4;
    const int nl  = tid & 15;

    float acc0[4] = {0.f, 0.f, 0.f, 0.f};
    float acc1[4] = {0.f, 0.f, 0.f, 0.f};

    for (int kt = 0; kt < 61; ++kt) {
        const int k0 = f0 + kt * 64;
        __syncthreads();
        for (int i = tid; i < 32 * 64; i += 256) {
            int r = i >> 6, c = i & 63;
            As[r * 68 + c] = g_flat[(size_t)(bc0 + r) * FLATN + k0 + c];
        }
        for (int i = tid; i < 64 * 64; i += 256) {
            int r = i >> 6, c = i & 63;
            Bs[i] = W1[(size_t)(k0 + r) * PREDN + n0 + c];
        }
        __syncthreads();
        #pragma unroll 8
        for (int kk = 0; kk < 64; ++kk) {
            float a0 = As[bg * 68 + kk];
            float a1 = As[(bg + 16) * 68 + kk];
            float4 b = *(const float4*)(Bs + kk * 64 + nl * 4);
            acc0[0] += a0 * b.x; acc0[1] += a0 * b.y; acc0[2] += a0 * b.z; acc0[3] += a0 * b.w;
            acc1[0] += a1 * b.x; acc1[1] += a1 * b.y; acc1[2] += a1 * b.z; acc1[3] += a1 * b.w;
        }
    }
    float* outp = g_hpart + ((size_t)blockIdx.z * BCN + bc0) * PREDN + n0 + nl * 4;
    *(float4*)(outp + (size_t)bg * PREDN)        = make_float4(acc0[0], acc0[1], acc0[2], acc0[3]);
    *(float4*)(outp + (size_t)(bg + 16) * PREDN) = make_float4(acc1[0], acc1[1], acc1[2], acc1[3]);
}

// ---------------- Kernel C2: reduce partials + bias + GELU + @W2 + bias -------
__global__ void mlp2_kernel(const float* __restrict__ b1, const float* __restrict__ W2,
                            const float* __restrict__ b2, float* __restrict__ out) {
    __shared__ float hs[2][PREDN];
    const int bc0 = blockIdx.x * 2;
    const int tid = threadIdx.x;   // 256

    for (int i = tid; i < 2 * PREDN; i += 256) {
        int r = i >> 8, n = i & 255;
        int bc = bc0 + r;
        float v = b1[n];
        #pragma unroll
        for (int ks = 0; ks < 4; ++ks)
            v += g_hpart[((size_t)ks * BCN + bc) * PREDN + n];
        hs[r][n] = 0.5f * v * (1.f + erff(v * 0.70710678118654752f));
    }
    __syncthreads();

    const int n = tid;
    float acc[2] = {0.f, 0.f};
    #pragma unroll 4
    for (int mm = 0; mm < PREDN; ++mm) {
        float w = W2[mm * PREDN + n];
        acc[0] += hs[0][mm] * w;
        acc[1] += hs[1][mm] * w;
    }
    float bb = b2[n];
    out[(size_t)bc0 * PREDN + n]       = acc[0] + bb;
    out[(size_t)(bc0 + 1) * PREDN + n] = acc[1] + bb;
}

// ---------------- launch ------------------------------------------------------
extern "C" void kernel_launch(void* const* d_in, const int* in_sizes, int n_in,
                              void* d_out, int out_size) {
    const float* lb  = (const float*)d_in[0];
    const float* fp  = (const float*)d_in[1];
    const float* Wp  = (const float*)d_in[2];
    const float* bp  = (const float*)d_in[3];
    const float* pe  = (const float*)d_in[4];
    const float* lng = (const float*)d_in[5];
    const float* lnb = (const float*)d_in[6];
    const float* W1  = (const float*)d_in[7];
    const float* b1  = (const float*)d_in[8];
    const float* W2  = (const float*)d_in[9];
    const float* b2  = (const float*)d_in[10];
    float* out = (float*)d_out;

    cudaFuncSetAttribute(attn_kernel, cudaFuncAttributeMaxDynamicSharedMemorySize,
                         ASM_BYTES);

    proj_ln_kernel<<<dim3((NROWS + A_ROWS - 1) / A_ROWS, BCN), 128>>>(lb, fp, Wp, bp, pe, lng, lnb);
    attn_kernel<<<dim3(2, BCN), 256, ASM_BYTES>>>(lb, fp);
    mlp1_kernel<<<dim3(4, 16, 4), 256>>>(W1);
    mlp2_kernel<<<BCN / 2, 256>>>(b1, W2, b2, out);
}

// round 3
// speedup vs baseline: 2.3384x; 1.5772x over previous
#include <cuda_runtime.h>
#include <cuda_bf16.h>
#include <math.h>
#include <stdint.h>

#define BCN   512          // B*C
#define LBK   1024
#define PREDN 256
#define TOT   1280
#define DEL   64
#define DPD   128
#define NKR   971          // key rows (T)
#define NQR   244          // query rows (UP)
#define NROWS 1215         // NKR + NQR
#define FLATN 15616        // NQR*DEL

// ---------------- scratch ------------------------------------------------------
__device__ __nv_bfloat16 g_khi[(size_t)BCN * NROWS * DPD];  // LN output, hi part
__device__ __nv_bfloat16 g_klo[(size_t)BCN * NROWS * DPD];  // LN output, lo part
__device__ float g_flat[(size_t)BCN * FLATN];               // attention outputs
__device__ float g_hpart[4 * BCN * PREDN];                  // split-K partials

__device__ __forceinline__ float series_at(const float* __restrict__ lb,
                                           const float* __restrict__ fp,
                                           int bc, int i) {
    return (i < LBK) ? lb[bc * LBK + i] : fp[bc * PREDN + (i - LBK)];
}

// ---------------- mma + split helpers -----------------------------------------
__device__ __forceinline__ void mma16(float c[4], const uint32_t a[4], const uint32_t b[2]) {
    asm volatile(
        "mma.sync.aligned.m16n8k16.row.col.f32.bf16.bf16.f32 "
        "{%0,%1,%2,%3}, {%4,%5,%6,%7}, {%8,%9}, {%0,%1,%2,%3};\n"
        : "+f"(c[0]), "+f"(c[1]), "+f"(c[2]), "+f"(c[3])
        : "r"(a[0]), "r"(a[1]), "r"(a[2]), "r"(a[3]), "r"(b[0]), "r"(b[1]));
}

// split (x0,x1) into packed bf16x2 hi and lo words
__device__ __forceinline__ void bsplit2(float x0, float x1, uint32_t& hi, uint32_t& lo) {
    __nv_bfloat16 h0 = __float2bfloat16(x0), h1 = __float2bfloat16(x1);
    __nv_bfloat16 l0 = __float2bfloat16(x0 - __bfloat162float(h0));
    __nv_bfloat16 l1 = __float2bfloat16(x1 - __bfloat162float(h1));
    __nv_bfloat162 H; H.x = h0; H.y = h1;
    __nv_bfloat162 L; L.x = l0; L.y = l1;
    hi = *(uint32_t*)&H; lo = *(uint32_t*)&L;
}

__device__ __forceinline__ void bsplit1(float x, __nv_bfloat16& h, __nv_bfloat16& l) {
    h = __float2bfloat16(x);
    l = __float2bfloat16(x - __bfloat162float(h));
}

// ---------------- Kernel A: proj + PE + LN on tensor cores --------------------
// A[128 rows][64] @ Wp[64][128] -> +bias +pe -> LayerNorm -> bf16 hi/lo planes
#define PKW 36                      // words per smem row (72 bf16)
#define PROJ_HDR_W (TOT + 256 + 256 + 128 + 128 + 128)   // 2176 words
#define PROJ_BYTES (PROJ_HDR_W * 4 + 4 * 128 * PKW * 4)  // 8704 + 73728 = 82432

__global__ void __launch_bounds__(256)
proj_ln_kernel(const float* __restrict__ lb, const float* __restrict__ fp,
               const float* __restrict__ Wp, const float* __restrict__ bp,
               const float* __restrict__ pe, const float* __restrict__ lng,
               const float* __restrict__ lnb) {
    extern __shared__ float psm[];
    float* ssp   = psm;                    // [TOT]
    float* red_s = ssp + TOT;              // [2][128]
    float* red_q = red_s + 256;            // [2][128]
    float* gl_s  = red_q + 256;            // [128]
    float* lb_s  = gl_s + 128;             // [128]
    float* bp_s  = lb_s + 128;             // [128]
    uint32_t* Ah = (uint32_t*)(bp_s + 128);    // [128][PKW]
    uint32_t* Al = Ah + 128 * PKW;
    uint32_t* Bh = Al + 128 * PKW;             // [n=128][k pad] words
    uint32_t* Bl = Bh + 128 * PKW;

    const int bc  = blockIdx.y;
    const int t0  = blockIdx.x * 128;
    const int tid = threadIdx.x;
    const int warp = tid >> 5, lane = tid & 31;
    const int g = lane >> 2, t = lane & 3;
    const int wm = warp >> 1, wn = warp & 1;
    const int R0 = wm * 32, C0 = wn * 64;

    for (int i = tid; i < TOT; i += 256) ssp[i] = series_at(lb, fp, bc, i);
    if (tid < 128) { gl_s[tid] = lng[tid]; lb_s[tid] = lnb[tid]; bp_s[tid] = bp[tid]; }
    __syncthreads();

    // build A (windows) split planes
    __nv_bfloat16* Ahb = (__nv_bfloat16*)Ah;
    __nv_bfloat16* Alb = (__nv_bfloat16*)Al;
    for (int i = tid; i < 128 * DEL; i += 256) {
        int r = i >> 6, d = i & 63;
        int tt = t0 + r;
        float x = 0.f;
        if (tt < NROWS) {
            int s0 = (tt < NKR) ? tt : (tt + 1);
            x = ssp[s0 + d];
        }
        __nv_bfloat16 h, l; bsplit1(x, h, l);
        Ahb[r * (2 * PKW) + d] = h;
        Alb[r * (2 * PKW) + d] = l;
    }
    // build B = Wp^T split planes: Bh[n][k]
    __nv_bfloat16* Bhb = (__nv_bfloat16*)Bh;
    __nv_bfloat16* Blb = (__nv_bfloat16*)Bl;
    for (int i = tid; i < DEL * DPD; i += 256) {
        int d = i >> 7, e = i & 127;
        float w = Wp[i];
        __nv_bfloat16 h, l; bsplit1(w, h, l);
        Bhb[e * (2 * PKW) + d] = h;
        Blb[e * (2 * PKW) + d] = l;
    }
    __syncthreads();

    // mma: warp tile 32 x 64, K = 64
    float cC[2][8][4];
    #pragma unroll
    for (int mi = 0; mi < 2; ++mi)
        #pragma unroll
        for (int ni = 0; ni < 8; ++ni)
            #pragma unroll
            for (int i = 0; i < 4; ++i) cC[mi][ni][i] = 0.f;

    #pragma unroll
    for (int e8 = 0; e8 < 4; ++e8) {
        uint32_t ah[2][4], al_[2][4];
        #pragma unroll
        for (int mi = 0; mi < 2; ++mi) {
            int r0 = (R0 + mi * 16 + g) * PKW + e8 * 8 + t;
            ah[mi][0] = Ah[r0];           ah[mi][1] = Ah[r0 + 8 * PKW];
            ah[mi][2] = Ah[r0 + 4];       ah[mi][3] = Ah[r0 + 8 * PKW + 4];
            al_[mi][0] = Al[r0];          al_[mi][1] = Al[r0 + 8 * PKW];
            al_[mi][2] = Al[r0 + 4];      al_[mi][3] = Al[r0 + 8 * PKW + 4];
        }
        uint32_t bh[8][2], bl2[8][2];
        #pragma unroll
        for (int ni = 0; ni < 8; ++ni) {
            int n0 = (C0 + ni * 8 + g) * PKW + e8 * 8 + t;
            bh[ni][0] = Bh[n0];  bh[ni][1] = Bh[n0 + 4];
            bl2[ni][0] = Bl[n0]; bl2[ni][1] = Bl[n0 + 4];
        }
        #pragma unroll
        for (int mi = 0; mi < 2; ++mi)
            #pragma unroll
            for (int ni = 0; ni < 8; ++ni) {
                mma16(cC[mi][ni], ah[mi], bh[ni]);
                mma16(cC[mi][ni], ah[mi], bl2[ni]);
                mma16(cC[mi][ni], al_[mi], bh[ni]);
            }
    }

    // epilogue: + bias + pe, LN partial sums
    float ps_[2][2], pq_[2][2];
    #pragma unroll
    for (int mi = 0; mi < 2; ++mi)
        #pragma unroll
        for (int h = 0; h < 2; ++h) { ps_[mi][h] = 0.f; pq_[mi][h] = 0.f; }

    #pragma unroll
    for (int mi = 0; mi < 2; ++mi)
        #pragma unroll
        for (int h = 0; h < 2; ++h) {
            int row = R0 + mi * 16 + g + 8 * h;
            int grow = t0 + row;
            const float* perow = pe + (size_t)grow * DPD;
            #pragma unroll
            for (int ni = 0; ni < 8; ++ni) {
                int col = C0 + ni * 8 + 2 * t;
                float2 p2 = *(const float2*)(perow + col);
                float x0 = cC[mi][ni][2 * h]     + bp_s[col]     + p2.x;
                float x1 = cC[mi][ni][2 * h + 1] + bp_s[col + 1] + p2.y;
                cC[mi][ni][2 * h] = x0; cC[mi][ni][2 * h + 1] = x1;
                ps_[mi][h] += x0 + x1;
                pq_[mi][h] += x0 * x0 + x1 * x1;
            }
        }
    #pragma unroll
    for (int mi = 0; mi < 2; ++mi)
        #pragma unroll
        for (int h = 0; h < 2; ++h) {
            ps_[mi][h] += __shfl_xor_sync(0xffffffffu, ps_[mi][h], 1);
            ps_[mi][h] += __shfl_xor_sync(0xffffffffu, ps_[mi][h], 2);
            pq_[mi][h] += __shfl_xor_sync(0xffffffffu, pq_[mi][h], 1);
            pq_[mi][h] += __shfl_xor_sync(0xffffffffu, pq_[mi][h], 2);
        }
    if (t == 0) {
        #pragma unroll
        for (int mi = 0; mi < 2; ++mi)
            #pragma unroll
            for (int h = 0; h < 2; ++h) {
                int row = R0 + mi * 16 + g + 8 * h;
                red_s[wn * 128 + row] = ps_[mi][h];
                red_q[wn * 128 + row] = pq_[mi][h];
            }
    }
    __syncthreads();

    #pragma unroll
    for (int mi = 0; mi < 2; ++mi)
        #pragma unroll
        for (int h = 0; h < 2; ++h) {
            int row = R0 + mi * 16 + g + 8 * h;
            int grow = t0 + row;
            if (grow >= NROWS) continue;
            float sm_ = red_s[row] + red_s[128 + row];
            float sq_ = red_q[row] + red_q[128 + row];
            float mean = sm_ * (1.f / DPD);
            float var  = sq_ * (1.f / DPD) - mean * mean;
            float inv  = rsqrtf(var + 1e-5f);
            size_t base = ((size_t)bc * NROWS + grow) * DPD;
            #pragma unroll
            for (int ni = 0; ni < 8; ++ni) {
                int col = C0 + ni * 8 + 2 * t;
                float y0 = (cC[mi][ni][2 * h]     - mean) * inv * gl_s[col]     + lb_s[col];
                float y1 = (cC[mi][ni][2 * h + 1] - mean) * inv * gl_s[col + 1] + lb_s[col + 1];
                uint32_t hw, lw; bsplit2(y0, y1, hw, lw);
                *(uint32_t*)(g_khi + base + col) = hw;
                *(uint32_t*)(g_klo + base + col) = lw;
            }
        }
}

// ---------------- Kernel B: flash attention, 2x-bf16 split mma ----------------
#define KW 68                        // words per smem row (136 bf16)
#define VPN 642
#define ATT_HDR_W (TOT + 4 * VPN + 3 * 128 + 512)   // 1280+2568+384+512 = 4744
#define ASM_BYTES (ATT_HDR_W * 4 + 4 * 128 * KW * 4)  // 18976 + 139264 = 158240

__global__ void __launch_bounds__(256, 1)
attn_kernel(const float* __restrict__ lb, const float* __restrict__ fp) {
    extern __shared__ float sm[];
    float* ss       = sm;                       // [TOT]
    uint32_t* vph   = (uint32_t*)(ss + TOT);    // [2][VPN]
    uint32_t* vpl   = vph + 2 * VPN;            // [2][VPN]
    float* m_s      = (float*)(vpl + 2 * VPN);  // [128]
    float* l_s      = m_s + 128;
    float* al_s     = l_s + 128;
    float* rmax_s   = al_s + 128;               // [2][128]
    float* rsum_s   = rmax_s + 256;             // [2][128]
    uint32_t* qh    = (uint32_t*)(rsum_s + 256);    // [128][KW]
    uint32_t* ql    = qh + 128 * KW;
    uint32_t* kh    = ql + 128 * KW;            // also P hi after softmax
    uint32_t* kl    = kh + 128 * KW;            // also P lo

    const int bc  = blockIdx.y;
    const int qt0 = blockIdx.x * 128;
    const int tid = threadIdx.x;
    const int warp = tid >> 5, lane = tid & 31;
    const int g = lane >> 2, t = lane & 3;

    const int s_q0 = (warp >> 1) * 32;
    const int s_k0 = (warp & 1) * 64;
    const int o_q0 = s_q0;
    const int o_d0 = (warp & 1) * 32;

    for (int i = tid; i < TOT; i += 256) ss[i] = series_at(lb, fp, bc, i);

    // load Q planes
    {
        const uint4* qhs = (const uint4*)(g_khi + ((size_t)bc * NROWS + NKR + qt0) * DPD);
        const uint4* qls = (const uint4*)(g_klo + ((size_t)bc * NROWS + NKR + qt0) * DPD);
        uint4 z = make_uint4(0u, 0u, 0u, 0u);
        for (int i = tid; i < 128 * 16; i += 256) {
            int r = i >> 4, c = i & 15;
            bool v = (qt0 + r) < NQR;
            ((uint4*)qh)[r * 17 + c] = v ? qhs[r * 16 + c] : z;
            ((uint4*)ql)[r * 17 + c] = v ? qls[r * 16 + c] : z;
        }
    }
    if (tid < 128) { m_s[tid] = -1e30f; l_s[tid] = 0.f; }
    __syncthreads();

    // build V parity-pair planes
    for (int i = tid; i < 2 * 641; i += 256) {
        int par = (i >= 641);
        int w = i - par * 641;
        int e0 = 2 * w + par;
        float x0 = (e0 < TOT) ? ss[e0] : 0.f;
        float x1 = (e0 + 1 < TOT) ? ss[e0 + 1] : 0.f;
        uint32_t hw, lw; bsplit2(x0, x1, hw, lw);
        vph[par * VPN + w] = hw;
        vpl[par * VPN + w] = lw;
    }

    float cO[2][4][4];
    #pragma unroll
    for (int mi = 0; mi < 2; ++mi)
        #pragma unroll
        for (int ni = 0; ni < 4; ++ni)
            #pragma unroll
            for (int i = 0; i < 4; ++i) cO[mi][ni][i] = 0.f;

    const float SCALE = 0.088388347648318447f;  // 1/sqrt(128)

    for (int kt0 = 0; kt0 < NKR; kt0 += 128) {
        __syncthreads();   // prior PV done -> safe to overwrite kh/kl
        {
            const uint4* khs = (const uint4*)(g_khi + ((size_t)bc * NROWS + kt0) * DPD);
            const uint4* kls = (const uint4*)(g_klo + ((size_t)bc * NROWS + kt0) * DPD);
            for (int i = tid; i < 128 * 16; i += 256) {
                int r = i >> 4, c = i & 15;
                ((uint4*)kh)[r * 17 + c] = khs[r * 16 + c];
                ((uint4*)kl)[r * 17 + c] = kls[r * 16 + c];
            }
        }
        __syncthreads();

        // ---- S = Q K^T ----
        float cS[2][8][4];
        #pragma unroll
        for (int mi = 0; mi < 2; ++mi)
            #pragma unroll
            for (int ni = 0; ni < 8; ++ni)
                #pragma unroll
                for (int i = 0; i < 4; ++i) cS[mi][ni][i] = 0.f;

        #pragma unroll
        for (int e8 = 0; e8 < 8; ++e8) {
            uint32_t ah[2][4], al_[2][4];
            #pragma unroll
            for (int mi = 0; mi < 2; ++mi) {
                int r0 = (s_q0 + mi * 16 + g) * KW + e8 * 8 + t;
                ah[mi][0] = qh[r0];          ah[mi][1] = qh[r0 + 8 * KW];
                ah[mi][2] = qh[r0 + 4];      ah[mi][3] = qh[r0 + 8 * KW + 4];
                al_[mi][0] = ql[r0];         al_[mi][1] = ql[r0 + 8 * KW];
                al_[mi][2] = ql[r0 + 4];     al_[mi][3] = ql[r0 + 8 * KW + 4];
            }
            uint32_t bh[8][2], bl2[8][2];
            #pragma unroll
            for (int ni = 0; ni < 8; ++ni) {
                int n0 = (s_k0 + ni * 8 + g) * KW + e8 * 8 + t;
                bh[ni][0] = kh[n0];  bh[ni][1] = kh[n0 + 4];
                bl2[ni][0] = kl[n0]; bl2[ni][1] = kl[n0 + 4];
            }
            #pragma unroll
            for (int mi = 0; mi < 2; ++mi)
                #pragma unroll
                for (int ni = 0; ni < 8; ++ni) {
                    mma16(cS[mi][ni], ah[mi], bh[ni]);
                    mma16(cS[mi][ni], ah[mi], bl2[ni]);
                    mma16(cS[mi][ni], al_[mi], bh[ni]);
                }
        }

        // ---- scale + mask + row max ----
        float rmx[2][2];
        #pragma unroll
        for (int mi = 0; mi < 2; ++mi) { rmx[mi][0] = -1e30f; rmx[mi][1] = -1e30f; }
        #pragma unroll
        for (int mi = 0; mi < 2; ++mi)
            #pragma unroll
            for (int ni = 0; ni < 8; ++ni)
                #pragma unroll
                for (int i = 0; i < 4; ++i) {
                    int col = s_k0 + ni * 8 + 2 * t + (i & 1);
                    float v = (kt0 + col < NKR) ? cS[mi][ni][i] * SCALE : -1e30f;
                    cS[mi][ni][i] = v;
                    rmx[mi][i >> 1] = fmaxf(rmx[mi][i >> 1], v);
                }
        #pragma unroll
        for (int mi = 0; mi < 2; ++mi)
            #pragma unroll
            for (int h = 0; h < 2; ++h) {
                rmx[mi][h] = fmaxf(rmx[mi][h], __shfl_xor_sync(0xffffffffu, rmx[mi][h], 1));
                rmx[mi][h] = fmaxf(rmx[mi][h], __shfl_xor_sync(0xffffffffu, rmx[mi][h], 2));
            }
        if (t == 0) {
            #pragma unroll
            for (int mi = 0; mi < 2; ++mi)
                #pragma unroll
                for (int h = 0; h < 2; ++h)
                    rmax_s[(warp & 1) * 128 + s_q0 + mi * 16 + g + h * 8] = rmx[mi][h];
        }
        __syncthreads();

        if (tid < 128) {
            float mo = m_s[tid];
            float mn = fmaxf(mo, fmaxf(rmax_s[tid], rmax_s[128 + tid]));
            al_s[tid] = __expf(mo - mn);
            m_s[tid] = mn;
        }
        __syncthreads();

        // ---- P = exp(S - m), split into kh/kl; row sums ----
        float mrow[2][2];
        #pragma unroll
        for (int mi = 0; mi < 2; ++mi)
            #pragma unroll
            for (int h = 0; h < 2; ++h)
                mrow[mi][h] = m_s[s_q0 + mi * 16 + g + h * 8];

        float rs[2][2] = {{0.f, 0.f}, {0.f, 0.f}};
        #pragma unroll
        for (int mi = 0; mi < 2; ++mi)
            #pragma unroll
            for (int ni = 0; ni < 8; ++ni) {
                float p0 = __expf(cS[mi][ni][0] - mrow[mi][0]);
                float p1 = __expf(cS[mi][ni][1] - mrow[mi][0]);
                float p2 = __expf(cS[mi][ni][2] - mrow[mi][1]);
                float p3 = __expf(cS[mi][ni][3] - mrow[mi][1]);
                rs[mi][0] += p0 + p1;
                rs[mi][1] += p2 + p3;
                int w0 = (s_q0 + mi * 16 + g) * KW + s_k0 / 2 + ni * 4 + t;
                uint32_t hw, lw;
                bsplit2(p0, p1, hw, lw);
                kh[w0] = hw; kl[w0] = lw;
                bsplit2(p2, p3, hw, lw);
                kh[w0 + 8 * KW] = hw; kl[w0 + 8 * KW] = lw;
            }
        #pragma unroll
        for (int mi = 0; mi < 2; ++mi)
            #pragma unroll
            for (int h = 0; h < 2; ++h) {
                rs[mi][h] += __shfl_xor_sync(0xffffffffu, rs[mi][h], 1);
                rs[mi][h] += __shfl_xor_sync(0xffffffffu, rs[mi][h], 2);
            }
        if (t == 0) {
            #pragma unroll
            for (int mi = 0; mi < 2; ++mi)
                #pragma unroll
                for (int h = 0; h < 2; ++h)
                    rsum_s[(warp & 1) * 128 + s_q0 + mi * 16 + g + h * 8] = rs[mi][h];
        }
        __syncthreads();

        if (tid < 128)
            l_s[tid] = l_s[tid] * al_s[tid] + rsum_s[tid] + rsum_s[128 + tid];

        // rescale O by alpha
        float af[2][2];
        #pragma unroll
        for (int mi = 0; mi < 2; ++mi)
            #pragma unroll
            for (int h = 0; h < 2; ++h)
                af[mi][h] = al_s[o_q0 + mi * 16 + g + h * 8];
        #pragma unroll
        for (int mi = 0; mi < 2; ++mi)
            #pragma unroll
            for (int ni = 0; ni < 4; ++ni)
                #pragma unroll
                for (int i = 0; i < 4; ++i)
                    cO[mi][ni][i] *= af[mi][i >> 1];

        // ---- O += P @ V ----
        const int vb0 = kt0 + 1;
        #pragma unroll
        for (int k8 = 0; k8 < 8; ++k8) {
            uint32_t ph[2][4], pl[2][4];
            #pragma unroll
            for (int mi = 0; mi < 2; ++mi) {
                int r0 = (o_q0 + mi * 16 + g) * KW + k8 * 8 + t;
                ph[mi][0] = kh[r0];          ph[mi][1] = kh[r0 + 8 * KW];
                ph[mi][2] = kh[r0 + 4];      ph[mi][3] = kh[r0 + 8 * KW + 4];
                pl[mi][0] = kl[r0];          pl[mi][1] = kl[r0 + 8 * KW];
                pl[mi][2] = kl[r0 + 4];      pl[mi][3] = kl[r0 + 8 * KW + 4];
            }
            uint32_t vh[4][2], vl[4][2];
            #pragma unroll
            for (int ni = 0; ni < 4; ++ni) {
                int d = o_d0 + ni * 8 + g;
                int idx0 = vb0 + k8 * 16 + 2 * t + d;
                int par = idx0 & 1;
                int w = (idx0 >> 1) + par * VPN;
                vh[ni][0] = vph[w];  vh[ni][1] = vph[w + 4];
                vl[ni][0] = vpl[w];  vl[ni][1] = vpl[w + 4];
            }
            #pragma unroll
            for (int mi = 0; mi < 2; ++mi)
                #pragma unroll
                for (int ni = 0; ni < 4; ++ni) {
                    mma16(cO[mi][ni], ph[mi], vh[ni]);
                    mma16(cO[mi][ni], ph[mi], vl[ni]);
                    mma16(cO[mi][ni], pl[mi], vh[ni]);
                }
        }
    }

    __syncthreads();
    float li[2][2];
    #pragma unroll
    for (int mi = 0; mi < 2; ++mi)
        #pragma unroll
        for (int h = 0; h < 2; ++h)
            li[mi][h] = 1.f / l_s[o_q0 + mi * 16 + g + h * 8];

    #pragma unroll
    for (int mi = 0; mi < 2; ++mi)
        #pragma unroll
        for (int ni = 0; ni < 4; ++ni) {
            int r0 = qt0 + o_q0 + mi * 16 + g;
            int d  = o_d0 + ni * 8 + 2 * t;
            if (r0 < NQR)
                *(float2*)(g_flat + (size_t)bc * FLATN + (size_t)r0 * DEL + d) =
                    make_float2(cO[mi][ni][0] * li[mi][0], cO[mi][ni][1] * li[mi][0]);
            if (r0 + 8 < NQR)
                *(float2*)(g_flat + (size_t)bc * FLATN + (size_t)(r0 + 8) * DEL + d) =
                    make_float2(cO[mi][ni][2] * li[mi][1], cO[mi][ni][3] * li[mi][1]);
        }
}

// ---------------- Kernel C1: flat @ W1 split-K partials -----------------------
__global__ void mlp1_kernel(const float* __restrict__ W1) {
    __shared__ float As[32 * 68];
    __shared__ float Bs[64 * 64];
    const int n0  = blockIdx.x * 64;
    const int bc0 = blockIdx.y * 32;
    const int f0  = blockIdx.z * 3904;
    const int tid = threadIdx.x;
    const int bg  = tid >> 4;
    const int nl  = tid & 15;

    float acc0[4] = {0.f, 0.f, 0.f, 0.f};
    float acc1[4] = {0.f, 0.f, 0.f, 0.f};

    for (int kt = 0; kt < 61; ++kt) {
        const int k0 = f0 + kt * 64;
        __syncthreads();
        for (int i = tid; i < 32 * 64; i += 256) {
            int r = i >> 6, c = i & 63;
            As[r * 68 + c] = g_flat[(size_t)(bc0 + r) * FLATN + k0 + c];
        }
        for (int i = tid; i < 64 * 64; i += 256) {
            int r = i >> 6, c = i & 63;
            Bs[i] = W1[(size_t)(k0 + r) * PREDN + n0 + c];
        }
        __syncthreads();
        #pragma unroll 8
        for (int kk = 0; kk < 64; ++kk) {
            float a0 = As[bg * 68 + kk];
            float a1 = As[(bg + 16) * 68 + kk];
            float4 b = *(const float4*)(Bs + kk * 64 + nl * 4);
            acc0[0] += a0 * b.x; acc0[1] += a0 * b.y; acc0[2] += a0 * b.z; acc0[3] += a0 * b.w;
            acc1[0] += a1 * b.x; acc1[1] += a1 * b.y; acc1[2] += a1 * b.z; acc1[3] += a1 * b.w;
        }
    }
    float* outp = g_hpart + ((size_t)blockIdx.z * BCN + bc0) * PREDN + n0 + nl * 4;
    *(float4*)(outp + (size_t)bg * PREDN)        = make_float4(acc0[0], acc0[1], acc0[2], acc0[3]);
    *(float4*)(outp + (size_t)(bg + 16) * PREDN) = make_float4(acc1[0], acc1[1], acc1[2], acc1[3]);
}

// ---------------- Kernel C2: reduce + GELU + @W2 ------------------------------
__global__ void mlp2_kernel(const float* __restrict__ b1, const float* __restrict__ W2,
                            const float* __restrict__ b2, float* __restrict__ out) {
    __shared__ float hs[2][PREDN];
    const int bc0 = blockIdx.x * 2;
    const int tid = threadIdx.x;   // 256

    for (int i = tid; i < 2 * PREDN; i += 256) {
        int r = i >> 8, n = i & 255;
        int bc = bc0 + r;
        float v = b1[n];
        #pragma unroll
        for (int ks = 0; ks < 4; ++ks)
            v += g_hpart[((size_t)ks * BCN + bc) * PREDN + n];
        hs[r][n] = 0.5f * v * (1.f + erff(v * 0.70710678118654752f));
    }
    __syncthreads();

    const int n = tid;
    float acc[2] = {0.f, 0.f};
    #pragma unroll 4
    for (int mm = 0; mm < PREDN; ++mm) {
        float w = W2[mm * PREDN + n];
        acc[0] += hs[0][mm] * w;
        acc[1] += hs[1][mm] * w;
    }
    float bb = b2[n];
    out[(size_t)bc0 * PREDN + n]       = acc[0] + bb;
    out[(size_t)(bc0 + 1) * PREDN + n] = acc[1] + bb;
}

// ---------------- launch ------------------------------------------------------
extern "C" void kernel_launch(void* const* d_in, const int* in_sizes, int n_in,
                              void* d_out, int out_size) {
    const float* lb  = (const float*)d_in[0];
    const float* fp  = (const float*)d_in[1];
    const float* Wp  = (const float*)d_in[2];
    const float* bp  = (const float*)d_in[3];
    const float* pe  = (const float*)d_in[4];
    const float* lng = (const float*)d_in[5];
    const float* lnb = (const float*)d_in[6];
    const float* W1  = (const float*)d_in[7];
    const float* b1  = (const float*)d_in[8];
    const float* W2  = (const float*)d_in[9];
    const float* b2  = (const float*)d_in[10];
    float* out = (float*)d_out;

    cudaFuncSetAttribute(proj_ln_kernel, cudaFuncAttributeMaxDynamicSharedMemorySize,
                         PROJ_BYTES);
    cudaFuncSetAttribute(attn_kernel, cudaFuncAttributeMaxDynamicSharedMemorySize,
                         ASM_BYTES);

    proj_ln_kernel<<<dim3(10, BCN), 256, PROJ_BYTES>>>(lb, fp, Wp, bp, pe, lng, lnb);
    attn_kernel<<<dim3(2, BCN), 256, ASM_BYTES>>>(lb, fp);
    mlp1_kernel<<<dim3(4, 16, 4), 256>>>(W1);
    mlp2_kernel<<<BCN / 2, 256>>>(b1, W2, b2, out);
}

// round 5
// speedup vs baseline: 2.6275x; 1.1236x over previous
#include <cuda_runtime.h>
#include <cuda_fp16.h>
#include <math.h>
#include <stdint.h>

#define BCN   512          // B*C
#define LBK   1024
#define PREDN 256
#define TOT   1280
#define DEL   64
#define DPD   128
#define NKR   971          // key rows (T)
#define NQR   244          // query rows (UP)
#define NROWS 1215         // NKR + NQR
#define FLATN 15616        // NQR*DEL
#define NSPL  8            // mlp1 split-K

// ---------------- scratch ------------------------------------------------------
__device__ __half g_kh[(size_t)BCN * NROWS * DPD];   // LN output, hi plane
__device__ __half g_kl[(size_t)BCN * NROWS * DPD];   // LN output, lo plane
__device__ __half g_fh[(size_t)BCN * FLATN];         // attention out, hi plane
__device__ __half g_fl[(size_t)BCN * FLATN];         // attention out, lo plane
__device__ __half g_w1h[(size_t)PREDN * FLATN];      // W1^T hi plane [n][k]
__device__ __half g_w1l[(size_t)PREDN * FLATN];      // W1^T lo plane [n][k]
__device__ float  g_hpart[NSPL * BCN * PREDN];       // split-K partials

__device__ __forceinline__ float series_at(const float* __restrict__ lb,
                                           const float* __restrict__ fp,
                                           int bc, int i) {
    return (i < LBK) ? lb[bc * LBK + i] : fp[bc * PREDN + (i - LBK)];
}

// ---------------- mma + split helpers -----------------------------------------
__device__ __forceinline__ void mma16(float c[4], const uint32_t a[4], const uint32_t b[2]) {
    asm volatile(
        "mma.sync.aligned.m16n8k16.row.col.f32.f16.f16.f32 "
        "{%0,%1,%2,%3}, {%4,%5,%6,%7}, {%8,%9}, {%0,%1,%2,%3};\n"
        : "+f"(c[0]), "+f"(c[1]), "+f"(c[2]), "+f"(c[3])
        : "r"(a[0]), "r"(a[1]), "r"(a[2]), "r"(a[3]), "r"(b[0]), "r"(b[1]));
}

// f16-accumulate variant (used for small correction terms)
__device__ __forceinline__ void mma16h(uint32_t c[2], const uint32_t a[4], const uint32_t b[2]) {
    asm volatile(
        "mma.sync.aligned.m16n8k16.row.col.f16.f16.f16.f16 "
        "{%0,%1}, {%2,%3,%4,%5}, {%6,%7}, {%0,%1};\n"
        : "+r"(c[0]), "+r"(c[1])
        : "r"(a[0]), "r"(a[1]), "r"(a[2]), "r"(a[3]), "r"(b[0]), "r"(b[1]));
}

__device__ __forceinline__ void merge_cor(float c[4], const uint32_t cor[2]) {
    float2 a = __half22float2(*(const __half2*)&cor[0]);
    float2 b = __half22float2(*(const __half2*)&cor[1]);
    c[0] += a.x; c[1] += a.y; c[2] += b.x; c[3] += b.y;
}

__device__ __forceinline__ void hsplit2(float x0, float x1, uint32_t& hi, uint32_t& lo) {
    __half h0 = __float2half_rn(x0), h1 = __float2half_rn(x1);
    __half l0 = __float2half_rn(x0 - __half2float(h0));
    __half l1 = __float2half_rn(x1 - __half2float(h1));
    __half2 H = __halves2half2(h0, h1), L = __halves2half2(l0, l1);
    hi = *(uint32_t*)&H; lo = *(uint32_t*)&L;
}

__device__ __forceinline__ void hsplit1(float x, __half& h, __half& l) {
    h = __float2half_rn(x);
    l = __float2half_rn(x - __half2float(h));
}

__device__ __forceinline__ float ex2(float x) {
    float r;
    asm("ex2.approx.f32 %0, %1;" : "=f"(r) : "f"(x));
    return r;
}

// ---------------- Kernel A: proj + PE + LN (fp16-split mma) -------------------
#define PKW 36
#define PROJ_HDR_W (TOT + 256 + 256 + 128 + 128 + 128)
#define PROJ_BYTES (PROJ_HDR_W * 4 + 4 * 128 * PKW * 4)

__global__ void __launch_bounds__(256)
proj_ln_kernel(const float* __restrict__ lb, const float* __restrict__ fp,
               const float* __restrict__ Wp, const float* __restrict__ bp,
               const float* __restrict__ pe, const float* __restrict__ lng,
               const float* __restrict__ lnb) {
    extern __shared__ float psm[];
    float* ssp   = psm;
    float* red_s = ssp + TOT;
    float* red_q = red_s + 256;
    float* gl_s  = red_q + 256;
    float* lb_s  = gl_s + 128;
    float* bp_s  = lb_s + 128;
    uint32_t* Ah = (uint32_t*)(bp_s + 128);
    uint32_t* Al = Ah + 128 * PKW;
    uint32_t* Bh = Al + 128 * PKW;
    uint32_t* Bl = Bh + 128 * PKW;

    const int bc  = blockIdx.y;
    const int t0  = blockIdx.x * 128;
    const int tid = threadIdx.x;
    const int warp = tid >> 5, lane = tid & 31;
    const int g = lane >> 2, t = lane & 3;
    const int wm = warp >> 1, wn = warp & 1;
    const int R0 = wm * 32, C0 = wn * 64;

    for (int i = tid; i < TOT; i += 256) ssp[i] = series_at(lb, fp, bc, i);
    if (tid < 128) { gl_s[tid] = lng[tid]; lb_s[tid] = lnb[tid]; bp_s[tid] = bp[tid]; }
    __syncthreads();

    __half* Ahb = (__half*)Ah;
    __half* Alb = (__half*)Al;
    for (int i = tid; i < 128 * DEL; i += 256) {
        int r = i >> 6, d = i & 63;
        int tt = t0 + r;
        float x = 0.f;
        if (tt < NROWS) {
            int s0 = (tt < NKR) ? tt : (tt + 1);
            x = ssp[s0 + d];
        }
        __half h, l; hsplit1(x, h, l);
        Ahb[r * (2 * PKW) + d] = h;
        Alb[r * (2 * PKW) + d] = l;
    }
    __half* Bhb = (__half*)Bh;
    __half* Blb = (__half*)Bl;
    for (int i = tid; i < DEL * DPD; i += 256) {
        int d = i >> 7, e = i & 127;
        float w = Wp[i];
        __half h, l; hsplit1(w, h, l);
        Bhb[e * (2 * PKW) + d] = h;
        Blb[e * (2 * PKW) + d] = l;
    }
    __syncthreads();

    float cC[2][8][4];
    uint32_t cr[2][8][2];
    #pragma unroll
    for (int mi = 0; mi < 2; ++mi)
        #pragma unroll
        for (int ni = 0; ni < 8; ++ni) {
            #pragma unroll
            for (int i = 0; i < 4; ++i) cC[mi][ni][i] = 0.f;
            cr[mi][ni][0] = 0u; cr[mi][ni][1] = 0u;
        }

    #pragma unroll
    for (int e8 = 0; e8 < 4; ++e8) {
        uint32_t ah[2][4], al_[2][4];
        #pragma unroll
        for (int mi = 0; mi < 2; ++mi) {
            int r0 = (R0 + mi * 16 + g) * PKW + e8 * 8 + t;
            ah[mi][0] = Ah[r0];           ah[mi][1] = Ah[r0 + 8 * PKW];
            ah[mi][2] = Ah[r0 + 4];       ah[mi][3] = Ah[r0 + 8 * PKW + 4];
            al_[mi][0] = Al[r0];          al_[mi][1] = Al[r0 + 8 * PKW];
            al_[mi][2] = Al[r0 + 4];      al_[mi][3] = Al[r0 + 8 * PKW + 4];
        }
        uint32_t bh[8][2], bl2[8][2];
        #pragma unroll
        for (int ni = 0; ni < 8; ++ni) {
            int n0 = (C0 + ni * 8 + g) * PKW + e8 * 8 + t;
            bh[ni][0] = Bh[n0];  bh[ni][1] = Bh[n0 + 4];
            bl2[ni][0] = Bl[n0]; bl2[ni][1] = Bl[n0 + 4];
        }
        #pragma unroll
        for (int mi = 0; mi < 2; ++mi)
            #pragma unroll
            for (int ni = 0; ni < 8; ++ni) {
                mma16(cC[mi][ni], ah[mi], bh[ni]);
                mma16h(cr[mi][ni], ah[mi], bl2[ni]);
                mma16h(cr[mi][ni], al_[mi], bh[ni]);
            }
    }
    #pragma unroll
    for (int mi = 0; mi < 2; ++mi)
        #pragma unroll
        for (int ni = 0; ni < 8; ++ni) merge_cor(cC[mi][ni], cr[mi][ni]);

    float ps_[2][2], pq_[2][2];
    #pragma unroll
    for (int mi = 0; mi < 2; ++mi)
        #pragma unroll
        for (int h = 0; h < 2; ++h) { ps_[mi][h] = 0.f; pq_[mi][h] = 0.f; }

    #pragma unroll
    for (int mi = 0; mi < 2; ++mi)
        #pragma unroll
        for (int h = 0; h < 2; ++h) {
            int row = R0 + mi * 16 + g + 8 * h;
            int grow = t0 + row;
            const float* perow = pe + (size_t)grow * DPD;
            #pragma unroll
            for (int ni = 0; ni < 8; ++ni) {
                int col = C0 + ni * 8 + 2 * t;
                float2 p2 = *(const float2*)(perow + col);
                float x0 = cC[mi][ni][2 * h]     + bp_s[col]     + p2.x;
                float x1 = cC[mi][ni][2 * h + 1] + bp_s[col + 1] + p2.y;
                cC[mi][ni][2 * h] = x0; cC[mi][ni][2 * h + 1] = x1;
                ps_[mi][h] += x0 + x1;
                pq_[mi][h] += x0 * x0 + x1 * x1;
            }
        }
    #pragma unroll
    for (int mi = 0; mi < 2; ++mi)
        #pragma unroll
        for (int h = 0; h < 2; ++h) {
            ps_[mi][h] += __shfl_xor_sync(0xffffffffu, ps_[mi][h], 1);
            ps_[mi][h] += __shfl_xor_sync(0xffffffffu, ps_[mi][h], 2);
            pq_[mi][h] += __shfl_xor_sync(0xffffffffu, pq_[mi][h], 1);
            pq_[mi][h] += __shfl_xor_sync(0xffffffffu, pq_[mi][h], 2);
        }
    if (t == 0) {
        #pragma unroll
        for (int mi = 0; mi < 2; ++mi)
            #pragma unroll
            for (int h = 0; h < 2; ++h) {
                int row = R0 + mi * 16 + g + 8 * h;
                red_s[wn * 128 + row] = ps_[mi][h];
                red_q[wn * 128 + row] = pq_[mi][h];
            }
    }
    __syncthreads();

    #pragma unroll
    for (int mi = 0; mi < 2; ++mi)
        #pragma unroll
        for (int h = 0; h < 2; ++h) {
            int row = R0 + mi * 16 + g + 8 * h;
            int grow = t0 + row;
            if (grow >= NROWS) continue;
            float sm_ = red_s[row] + red_s[128 + row];
            float sq_ = red_q[row] + red_q[128 + row];
            float mean = sm_ * (1.f / DPD);
            float var  = sq_ * (1.f / DPD) - mean * mean;
            float inv  = rsqrtf(var + 1e-5f);
            size_t base = ((size_t)bc * NROWS + grow) * DPD;
            #pragma unroll
            for (int ni = 0; ni < 8; ++ni) {
                int col = C0 + ni * 8 + 2 * t;
                float y0 = (cC[mi][ni][2 * h]     - mean) * inv * gl_s[col]     + lb_s[col];
                float y1 = (cC[mi][ni][2 * h + 1] - mean) * inv * gl_s[col + 1] + lb_s[col + 1];
                uint32_t hw, lw; hsplit2(y0, y1, hw, lw);
                *(uint32_t*)(g_kh + base + col) = hw;
                *(uint32_t*)(g_kl + base + col) = lw;
            }
        }
}

// ---------------- Kernel B: flash attention, fp16-split mma, fixed-offset sm --
#define KW 68
#define VPN 642
#define ATT_HDR_W (TOT + 4 * VPN + 256)
#define ASM_BYTES (ATT_HDR_W * 4 + 4 * 128 * KW * 4)

__global__ void __launch_bounds__(256, 1)
attn_kernel(const float* __restrict__ lb, const float* __restrict__ fp) {
    extern __shared__ float sm[];
    float* ss       = sm;                       // [TOT]
    uint32_t* vph   = (uint32_t*)(ss + TOT);    // [2][VPN]
    uint32_t* vpl   = vph + 2 * VPN;            // [2][VPN]
    float* lred     = (float*)(vpl + 2 * VPN);  // [2][128]
    uint32_t* qh    = (uint32_t*)(lred + 256);  // [128][KW]
    uint32_t* ql    = qh + 128 * KW;
    uint32_t* kh    = ql + 128 * KW;            // K chunk, then P hi
    uint32_t* kl    = kh + 128 * KW;            // K chunk, then P lo

    const int bc  = blockIdx.y;
    const int qt0 = blockIdx.x * 128;
    const int tid = threadIdx.x;
    const int warp = tid >> 5, lane = tid & 31;
    const int g = lane >> 2, t = lane & 3;

    const int s_q0 = (warp >> 1) * 32;
    const int s_k0 = (warp & 1) * 64;
    const int o_q0 = s_q0;
    const int o_d0 = (warp & 1) * 32;

    for (int i = tid; i < TOT; i += 256) ss[i] = series_at(lb, fp, bc, i);

    // load Q planes (rows: 128 halves = 16B*... 64 words = 16 uint4)
    {
        const uint4* qhs = (const uint4*)(g_kh + ((size_t)bc * NROWS + NKR + qt0) * DPD);
        const uint4* qls = (const uint4*)(g_kl + ((size_t)bc * NROWS + NKR + qt0) * DPD);
        uint4 z = make_uint4(0u, 0u, 0u, 0u);
        for (int i = tid; i < 128 * 16; i += 256) {
            int r = i >> 4, c = i & 15;
            bool v = (qt0 + r) < NQR;
            ((uint4*)qh)[r * 17 + c] = v ? qhs[r * 16 + c] : z;
            ((uint4*)ql)[r * 17 + c] = v ? qls[r * 16 + c] : z;
        }
    }
    __syncthreads();

    // V parity-pair planes (built once)
    for (int i = tid; i < 2 * 641; i += 256) {
        int par = (i >= 641);
        int w = i - par * 641;
        int e0 = 2 * w + par;
        float x0 = (e0 < TOT) ? ss[e0] : 0.f;
        float x1 = (e0 + 1 < TOT) ? ss[e0 + 1] : 0.f;
        uint32_t hw, lw; hsplit2(x0, x1, hw, lw);
        vph[par * VPN + w] = hw;
        vpl[par * VPN + w] = lw;
    }

    float cO[2][4][4];
    uint32_t crO[2][4][2];
    float rs_reg[2][2] = {{0.f, 0.f}, {0.f, 0.f}};
    #pragma unroll
    for (int mi = 0; mi < 2; ++mi)
        #pragma unroll
        for (int ni = 0; ni < 4; ++ni) {
            #pragma unroll
            for (int i = 0; i < 4; ++i) cO[mi][ni][i] = 0.f;
            crO[mi][ni][0] = 0u; crO[mi][ni][1] = 0u;
        }

    const float C2  = 0.1275174324f;     // log2(e)/sqrt(128)
    const float OFF = -8.6561702453f;    // -6*log2(e)

    for (int kt0 = 0; kt0 < NKR; kt0 += 128) {
        __syncthreads();   // prior PV reads done -> safe to overwrite kh/kl
        {
            const uint4* khs = (const uint4*)(g_kh + ((size_t)bc * NROWS + kt0) * DPD);
            const uint4* kls = (const uint4*)(g_kl + ((size_t)bc * NROWS + kt0) * DPD);
            uint4 z = make_uint4(0u, 0u, 0u, 0u);
            for (int i = tid; i < 128 * 16; i += 256) {
                int r = i >> 4, c = i & 15;
                bool v = (kt0 + r) < NKR;
                ((uint4*)kh)[r * 17 + c] = v ? khs[r * 16 + c] : z;
                ((uint4*)kl)[r * 17 + c] = v ? kls[r * 16 + c] : z;
            }
        }
        __syncthreads();

        // ---- S = Q K^T ----
        float cS[2][8][4];
        uint32_t crS[2][8][2];
        #pragma unroll
        for (int mi = 0; mi < 2; ++mi)
            #pragma unroll
            for (int ni = 0; ni < 8; ++ni) {
                #pragma unroll
                for (int i = 0; i < 4; ++i) cS[mi][ni][i] = 0.f;
                crS[mi][ni][0] = 0u; crS[mi][ni][1] = 0u;
            }

        #pragma unroll
        for (int e8 = 0; e8 < 8; ++e8) {
            uint32_t ah[2][4], al_[2][4];
            #pragma unroll
            for (int mi = 0; mi < 2; ++mi) {
                int r0 = (s_q0 + mi * 16 + g) * KW + e8 * 8 + t;
                ah[mi][0] = qh[r0];          ah[mi][1] = qh[r0 + 8 * KW];
                ah[mi][2] = qh[r0 + 4];      ah[mi][3] = qh[r0 + 8 * KW + 4];
                al_[mi][0] = ql[r0];         al_[mi][1] = ql[r0 + 8 * KW];
                al_[mi][2] = ql[r0 + 4];     al_[mi][3] = ql[r0 + 8 * KW + 4];
            }
            uint32_t bh[8][2], bl2[8][2];
            #pragma unroll
            for (int ni = 0; ni < 8; ++ni) {
                int n0 = (s_k0 + ni * 8 + g) * KW + e8 * 8 + t;
                bh[ni][0] = kh[n0];  bh[ni][1] = kh[n0 + 4];
                bl2[ni][0] = kl[n0]; bl2[ni][1] = kl[n0 + 4];
            }
            #pragma unroll
            for (int mi = 0; mi < 2; ++mi)
                #pragma unroll
                for (int ni = 0; ni < 8; ++ni) {
                    mma16(cS[mi][ni], ah[mi], bh[ni]);
                    mma16h(crS[mi][ni], ah[mi], bl2[ni]);
                    mma16h(crS[mi][ni], al_[mi], bh[ni]);
                }
        }
        __syncthreads();   // all warps done reading kh/kl (K) before P overwrite

        // ---- P = exp(s*scale - 6), write to kh/kl, accumulate row sums -------
        #pragma unroll
        for (int mi = 0; mi < 2; ++mi)
            #pragma unroll
            for (int ni = 0; ni < 8; ++ni) {
                merge_cor(cS[mi][ni], crS[mi][ni]);
                int c0 = kt0 + s_k0 + ni * 8 + 2 * t;
                float p0 = (c0     < NKR) ? ex2(fmaf(cS[mi][ni][0], C2, OFF)) : 0.f;
                float p1 = (c0 + 1 < NKR) ? ex2(fmaf(cS[mi][ni][1], C2, OFF)) : 0.f;
                float p2 = (c0     < NKR) ? ex2(fmaf(cS[mi][ni][2], C2, OFF)) : 0.f;
                float p3 = (c0 + 1 < NKR) ? ex2(fmaf(cS[mi][ni][3], C2, OFF)) : 0.f;
                rs_reg[mi][0] += p0 + p1;
                rs_reg[mi][1] += p2 + p3;
                int w0 = (s_q0 + mi * 16 + g) * KW + (s_k0 >> 1) + ni * 4 + t;
                uint32_t hw, lw;
                hsplit2(p0, p1, hw, lw);
                kh[w0] = hw; kl[w0] = lw;
                hsplit2(p2, p3, hw, lw);
                kh[w0 + 8 * KW] = hw; kl[w0 + 8 * KW] = lw;
            }
        __syncthreads();   // P visible to all warps

        // ---- O += P @ V ----
        const int vb0 = kt0 + 1;
        #pragma unroll
        for (int k8 = 0; k8 < 8; ++k8) {
            uint32_t ph[2][4], pl[2][4];
            #pragma unroll
            for (int mi = 0; mi < 2; ++mi) {
                int r0 = (o_q0 + mi * 16 + g) * KW + k8 * 8 + t;
                ph[mi][0] = kh[r0];          ph[mi][1] = kh[r0 + 8 * KW];
                ph[mi][2] = kh[r0 + 4];      ph[mi][3] = kh[r0 + 8 * KW + 4];
                pl[mi][0] = kl[r0];          pl[mi][1] = kl[r0 + 8 * KW];
                pl[mi][2] = kl[r0 + 4];      pl[mi][3] = kl[r0 + 8 * KW + 4];
            }
            uint32_t vh[4][2], vl[4][2];
            #pragma unroll
            for (int ni = 0; ni < 4; ++ni) {
                int d = o_d0 + ni * 8 + g;
                int idx0 = vb0 + k8 * 16 + 2 * t + d;
                int par = idx0 & 1;
                int w = (idx0 >> 1) + par * VPN;
                vh[ni][0] = vph[w];  vh[ni][1] = vph[w + 4];
                vl[ni][0] = vpl[w];  vl[ni][1] = vpl[w + 4];
            }
            #pragma unroll
            for (int mi = 0; mi < 2; ++mi)
                #pragma unroll
                for (int ni = 0; ni < 4; ++ni) {
                    mma16(cO[mi][ni], ph[mi], vh[ni]);
                    mma16h(crO[mi][ni], ph[mi], vl[ni]);
                    mma16h(crO[mi][ni], pl[mi], vh[ni]);
                }
        }
    }

    // ---- final l reduction + output ----
    #pragma unroll
    for (int mi = 0; mi < 2; ++mi)
        #pragma unroll
        for (int h = 0; h < 2; ++h) {
            rs_reg[mi][h] += __shfl_xor_sync(0xffffffffu, rs_reg[mi][h], 1);
            rs_reg[mi][h] += __shfl_xor_sync(0xffffffffu, rs_reg[mi][h], 2);
        }
    __syncthreads();
    if (t == 0) {
        #pragma unroll
        for (int mi = 0; mi < 2; ++mi)
            #pragma unroll
            for (int h = 0; h < 2; ++h)
                lred[(warp & 1) * 128 + s_q0 + mi * 16 + g + h * 8] = rs_reg[mi][h];
    }
    __syncthreads();

    #pragma unroll
    for (int mi = 0; mi < 2; ++mi)
        #pragma unroll
        for (int ni = 0; ni < 4; ++ni) {
            merge_cor(cO[mi][ni], crO[mi][ni]);
            int row0 = o_q0 + mi * 16 + g;
            float inv0 = 1.f / (lred[row0] + lred[128 + row0]);
            float inv1 = 1.f / (lred[row0 + 8] + lred[136 + row0]);
            int r0 = qt0 + row0;
            int d  = o_d0 + ni * 8 + 2 * t;
            uint32_t hw, lw;
            if (r0 < NQR) {
                hsplit2(cO[mi][ni][0] * inv0, cO[mi][ni][1] * inv0, hw, lw);
                *(uint32_t*)(g_fh + (size_t)bc * FLATN + (size_t)r0 * DEL + d) = hw;
                *(uint32_t*)(g_fl + (size_t)bc * FLATN + (size_t)r0 * DEL + d) = lw;
            }
            if (r0 + 8 < NQR) {
                hsplit2(cO[mi][ni][2] * inv1, cO[mi][ni][3] * inv1, hw, lw);
                *(uint32_t*)(g_fh + (size_t)bc * FLATN + (size_t)(r0 + 8) * DEL + d) = hw;
                *(uint32_t*)(g_fl + (size_t)bc * FLATN + (size_t)(r0 + 8) * DEL + d) = lw;
            }
        }
}

// ---------------- Kernel W: split W1 into transposed fp16 planes --------------
__global__ void __launch_bounds__(256)
conv_w1_kernel(const float* __restrict__ W1) {
    int gid = blockIdx.x * 256 + threadIdx.x;   // over 15616*64 float4s
    int k  = gid >> 6;
    int n4 = (gid & 63) << 2;
    float4 w = *(const float4*)(W1 + (size_t)k * PREDN + n4);
    float v[4] = {w.x, w.y, w.z, w.w};
    #pragma unroll
    for (int j = 0; j < 4; ++j) {
        __half h, l; hsplit1(v[j], h, l);
        g_w1h[(size_t)(n4 + j) * FLATN + k] = h;
        g_w1l[(size_t)(n4 + j) * FLATN + k] = l;
    }
}

// ---------------- Kernel C1: flat @ W1 split-K, fp16-split mma ----------------
#define MROW 20   // smem row stride in words (32 halves data + pad)
__global__ void __launch_bounds__(256)
mlp1_kernel() {
    __shared__ __align__(16) uint32_t Ah[64 * MROW];
    __shared__ __align__(16) uint32_t Al[64 * MROW];
    __shared__ __align__(16) uint32_t Bh[64 * MROW];
    __shared__ __align__(16) uint32_t Bl[64 * MROW];

    const int n0  = blockIdx.x * 64;
    const int bc0 = blockIdx.y * 64;
    const int z   = blockIdx.z;            // split-K index (k extent 1952)
    const int tid = threadIdx.x;
    const int warp = tid >> 5, lane = tid & 31;
    const int g = lane >> 2, t = lane & 3;
    const int m0  = (warp >> 1) * 16;
    const int n0w = (warp & 1) * 32;

    const int r4 = tid >> 2, c4 = tid & 3;   // loader: one uint4 per plane

    float cM[4][4];
    uint32_t crM[4][2];
    #pragma unroll
    for (int ni = 0; ni < 4; ++ni) {
        #pragma unroll
        for (int i = 0; i < 4; ++i) cM[ni][i] = 0.f;
        crM[ni][0] = 0u; crM[ni][1] = 0u;
    }

    for (int ch = 0; ch < 61; ++ch) {
        const int k0 = z * 1952 + ch * 32;
        __syncthreads();
        {
            const uint4* ah = (const uint4*)(g_fh + (size_t)(bc0 + r4) * FLATN + k0);
            const uint4* al = (const uint4*)(g_fl + (size_t)(bc0 + r4) * FLATN + k0);
            const uint4* bh = (const uint4*)(g_w1h + (size_t)(n0 + r4) * FLATN + k0);
            const uint4* bl = (const uint4*)(g_w1l + (size_t)(n0 + r4) * FLATN + k0);
            ((uint4*)Ah)[r4 * 5 + c4] = ah[c4];
            ((uint4*)Al)[r4 * 5 + c4] = al[c4];
            ((uint4*)Bh)[r4 * 5 + c4] = bh[c4];
            ((uint4*)Bl)[r4 * 5 + c4] = bl[c4];
        }
        __syncthreads();

        #pragma unroll
        for (int s = 0; s < 2; ++s) {
            uint32_t ah[4], al_[4];
            {
                int base = (m0 + g) * MROW + s * 8 + t;
                ah[0] = Ah[base];               ah[1] = Ah[base + 8 * MROW];
                ah[2] = Ah[base + 4];           ah[3] = Ah[base + 8 * MROW + 4];
                al_[0] = Al[base];              al_[1] = Al[base + 8 * MROW];
                al_[2] = Al[base + 4];          al_[3] = Al[base + 8 * MROW + 4];
            }
            uint32_t bh[4][2], bl2[4][2];
            #pragma unroll
            for (int ni = 0; ni < 4; ++ni) {
                int nb = (n0w + ni * 8 + g) * MROW + s * 8 + t;
                bh[ni][0] = Bh[nb];  bh[ni][1] = Bh[nb + 4];
                bl2[ni][0] = Bl[nb]; bl2[ni][1] = Bl[nb + 4];
            }
            #pragma unroll
            for (int ni = 0; ni < 4; ++ni) {
                mma16(cM[ni], ah, bh[ni]);
                mma16h(crM[ni], ah, bl2[ni]);
                mma16h(crM[ni], al_, bh[ni]);
            }
        }
    }

    #pragma unroll
    for (int ni = 0; ni < 4; ++ni) {
        merge_cor(cM[ni], crM[ni]);
        int col = n0 + n0w + ni * 8 + 2 * t;
        *(float2*)(g_hpart + ((size_t)z * BCN + bc0 + m0 + g) * PREDN + col) =
            make_float2(cM[ni][0], cM[ni][1]);
        *(float2*)(g_hpart + ((size_t)z * BCN + bc0 + m0 + g + 8) * PREDN + col) =
            make_float2(cM[ni][2], cM[ni][3]);
    }
}

// ---------------- Kernel C2: reduce + GELU + @W2 ------------------------------
__global__ void __launch_bounds__(256)
mlp2_kernel(const float* __restrict__ b1, const float* __restrict__ W2,
            const float* __restrict__ b2, float* __restrict__ out) {
    __shared__ float hs[2][PREDN];
    const int bc0 = blockIdx.x * 2;
    const int nh  = blockIdx.y;
    const int tid = threadIdx.x;   // 256

    for (int i = tid; i < 2 * PREDN; i += 256) {
        int r = i >> 8, n = i & 255;
        int bc = bc0 + r;
        float v = b1[n];
        #pragma unroll
        for (int ks = 0; ks < NSPL; ++ks)
            v += g_hpart[((size_t)ks * BCN + bc) * PREDN + n];
        hs[r][n] = 0.5f * v * (1.f + erff(v * 0.70710678118654752f));
    }
    __syncthreads();

    const int r = tid >> 7;
    const int n = nh * 128 + (tid & 127);
    float acc = 0.f;
    #pragma unroll 4
    for (int k = 0; k < PREDN; ++k)
        acc += hs[r][k] * W2[k * PREDN + n];
    out[(size_t)(bc0 + r) * PREDN + n] = acc + b2[n];
}

// ---------------- launch ------------------------------------------------------
extern "C" void kernel_launch(void* const* d_in, const int* in_sizes, int n_in,
                              void* d_out, int out_size) {
    const float* lb  = (const float*)d_in[0];
    const float* fp  = (const float*)d_in[1];
    const float* Wp  = (const float*)d_in[2];
    const float* bp  = (const float*)d_in[3];
    const float* pe  = (const float*)d_in[4];
    const float* lng = (const float*)d_in[5];
    const float* lnb = (const float*)d_in[6];
    const float* W1  = (const float*)d_in[7];
    const float* b1  = (const float*)d_in[8];
    const float* W2  = (const float*)d_in[9];
    const float* b2  = (const float*)d_in[10];
    float* out = (float*)d_out;

    cudaFuncSetAttribute(proj_ln_kernel, cudaFuncAttributeMaxDynamicSharedMemorySize,
                         PROJ_BYTES);
    cudaFuncSetAttribute(attn_kernel, cudaFuncAttributeMaxDynamicSharedMemorySize,
                         ASM_BYTES);

    conv_w1_kernel<<<FLATN * 64 / 256, 256>>>(W1);
    proj_ln_kernel<<<dim3(10, BCN), 256, PROJ_BYTES>>>(lb, fp, Wp, bp, pe, lng, lnb);
    attn_kernel<<<dim3(2, BCN), 256, ASM_BYTES>>>(lb, fp);
    mlp1_kernel<<<dim3(4, 8, NSPL), 256>>>();
    mlp2_kernel<<<dim3(BCN / 2, 2), 256>>>(b1, W2, b2, out);
}